// round 8
// baseline (speedup 1.0000x reference)
#include <cuda_runtime.h>
#include <cuda_fp16.h>
#include <cstdint>
#include <math.h>

#define B_      64
#define L_      2048
#define DTS     8
#define DSEQ    120
#define DIN     128
#define H_      64
#define NSPLIT  8
#define TILE_B  256              // tokens per block
#define TILE_M  128              // tokens per MMA tile
#define TPB     256
#define SLOPE   0.2291666666666667f

// smem layout (bytes)
#define HDR     5120
#define X0_OFF  5120
#define X1_OFF  37888
#define WH_OFF  70656
#define SMEM_TOTAL 103424        // 2 blocks/SM

__device__ float g_m[B_ * NSPLIT];
__device__ float g_s[B_ * NSPLIT];
__device__ float g_acc[B_ * NSPLIT * H_];
__device__ int   g_cnt[B_];      // zero-init; self-resetting per replay

__device__ __forceinline__ uint32_t smem_u32(const void* p) {
    uint32_t a;
    asm("{ .reg .u64 t; cvta.to.shared.u64 t, %1; cvt.u32.u64 %0, t; }" : "=r"(a) : "l"(p));
    return a;
}
__device__ __forceinline__ float rrelu(float x) { return x >= 0.f ? x : x * SLOPE; }
__device__ __forceinline__ uint32_t cvt_h2(float f0, float f1) {
    __half2 hh = __floats2half2_rn(f0, f1);
    return *reinterpret_cast<uint32_t*>(&hh);
}

#define BAR_SYNC(id, cnt)   asm volatile("bar.sync %0, %1;"   :: "r"(id), "r"(cnt) : "memory")
#define BAR_ARRIVE(id, cnt) asm volatile("bar.arrive %0, %1;" :: "r"(id), "r"(cnt) : "memory")
#define MEMBAR_CTA()        asm volatile("membar.cta;" ::: "memory")

#define LDSM_X4(r0, r1, r2, r3, addr) \
    asm volatile("ldmatrix.sync.aligned.m8n8.x4.shared.b16 {%0,%1,%2,%3}, [%4];" \
        : "=r"(r0), "=r"(r1), "=r"(r2), "=r"(r3) : "r"(addr))
#define LDSM_X4_T(r0, r1, r2, r3, addr) \
    asm volatile("ldmatrix.sync.aligned.m8n8.x4.trans.shared.b16 {%0,%1,%2,%3}, [%4];" \
        : "=r"(r0), "=r"(r1), "=r"(r2), "=r"(r3) : "r"(addr))

__device__ __forceinline__ void mma_f16(float (&c)[4], uint32_t a0, uint32_t a1,
                                        uint32_t a2, uint32_t a3,
                                        uint32_t b0, uint32_t b1) {
    asm volatile(
        "mma.sync.aligned.m16n8k16.row.col.f32.f16.f16.f32 "
        "{%0,%1,%2,%3}, {%4,%5,%6,%7}, {%8,%9}, {%0,%1,%2,%3};"
        : "+f"(c[0]), "+f"(c[1]), "+f"(c[2]), "+f"(c[3])
        : "r"(a0), "r"(a1), "r"(a2), "r"(a3), "r"(b0), "r"(b1));
}

// ---------------------------------------------------------------------------
// fused: per (split, batch) block — 256-token span, two 128-row MMA tiles.
// Decoupled pipelines: K-warps (0-3) produce scores+softmax; V-warps (4-7)
// GEMM V and consume softmax weights via named-barrier handoff.
// ---------------------------------------------------------------------------
__global__ void __launch_bounds__(TPB, 2)
fused_attn(const float* __restrict__ ts, const float* __restrict__ seq,
           const int* __restrict__ lengths,
           const float* __restrict__ Wk, const float* __restrict__ bk,
           const float* __restrict__ Wq, const float* __restrict__ bq,
           const float* __restrict__ Wv, const float* __restrict__ bv,
           float* __restrict__ out) {
    int b   = blockIdx.y;
    int sp  = blockIdx.x;
    int len = lengths[b];
    int start = sp * TILE_B;
    int tid = threadIdx.x;
    int wid = tid >> 5, lane = tid & 31;
    int idx = b * NSPLIT + sp;
    int nlive = min(NSPLIT, (len + TILE_B - 1) / TILE_B);

    if (sp >= nlive) return;   // dead split
    int ntiles = min(2, (len - start + TILE_M - 1) >> 7);

    extern __shared__ char smem[];
    uint32_t sb = smem_u32(smem);
    float* sQ      = (float*)smem;             // 64
    float* sQpart  = (float*)(smem + 256);     // 128
    float* sBias   = (float*)(smem + 768);     // 128
    float* sXlast  = (float*)(smem + 1280);    // 128
    float* sScore0 = (float*)(smem + 1792);    // 128
    float* sScore1 = (float*)(smem + 2304);    // 128
    float* sRed0   = (float*)(smem + 2816);    // 256
    float* sRed1   = (float*)(smem + 3840);    // 256
    float* sM      = (float*)(smem + 4864);    // 2
    float* sSum    = (float*)(smem + 4872);    // 2
    int*   sLast   = (int*)(smem + 4880);

    // ---- bias + last-token row + tile-1 neutral init ----
    if (tid < DIN) {
        sBias[tid] = (tid < H_) ? bk[tid] : bv[tid - H_];
        int l = len - 1;
        sXlast[tid] = (tid < DTS) ? ts[((size_t)b * L_ + l) * DTS + tid]
                                  : seq[((size_t)b * L_ + l) * DSEQ + (tid - DTS)];
    }
    if (tid == 255) { sM[1] = -INFINITY; sSum[1] = 0.f; }

    // ---- W tile: [Wk | Wv] fp32 -> fp16, swizzled ----
#pragma unroll
    for (int it = 0; it < 8; ++it) {
        int j = tid + it * TPB;               // 0..2047
        int k = j >> 4, ch = j & 15;
        int n0 = ch * 8;
        const float* src = (n0 < H_) ? (Wk + k * H_ + n0) : (Wv + k * H_ + n0 - H_);
        float4 f0 = ((const float4*)src)[0];
        float4 f1 = ((const float4*)src)[1];
        uint4 v = make_uint4(cvt_h2(f0.x, f0.y), cvt_h2(f0.z, f0.w),
                             cvt_h2(f1.x, f1.y), cvt_h2(f1.z, f1.w));
        uint32_t off = (uint32_t)(k * 256 + ((ch ^ (k & 7)) << 4));
        *(uint4*)(smem + WH_OFF + off) = v;
    }

    // ---- X tiles (front-batched): fp32 -> fp16, swizzled ----
    for (int tl = 0; tl < ntiles; ++tl) {
        int xoff = X0_OFF + tl * 32768;
        int tbase = start + tl * TILE_M;
#pragma unroll
        for (int it = 0; it < 8; ++it) {
            int j = tid + it * TPB;           // 0..2047
            int row = j >> 4, ch = j & 15;
            int token = tbase + row;
            const float* src = (ch == 0)
                ? (ts + ((size_t)b * L_ + token) * DTS)
                : (seq + ((size_t)b * L_ + token) * DSEQ + (ch * 8 - 8));
            float4 f0 = ((const float4*)src)[0];
            float4 f1 = ((const float4*)src)[1];
            uint4 v = make_uint4(cvt_h2(f0.x, f0.y), cvt_h2(f0.z, f0.w),
                                 cvt_h2(f1.x, f1.y), cvt_h2(f1.z, f1.w));
            uint32_t off = (uint32_t)(row * 256 + ((ch ^ (row & 7)) << 4));
            *(uint4*)(smem + xoff + off) = v;
        }
    }
    __syncthreads();

    int kw = wid & 3;
    int isV = wid >> 2;
    uint32_t nchunk = (uint32_t)(isV << 3);

    int li = lane >> 3, lr = lane & 7;
    int roff = ((li & 1) << 3) + lr;
    int ci   = li >> 1;
    int rm   = roff & 7;
    int g = lane >> 2, t = lane & 3;

    if (!isV) {
        // =================== K-warp pipeline (warps 0-3) ===================
        // q partials: 128 threads, part = tid>>6 (0/1), 64 d's each, coalesced
        {
            int h = tid & 63, part = tid >> 6;
            float s = 0.f;
            const float* wq = Wq + part * 64 * H_ + h;
#pragma unroll 8
            for (int d = 0; d < 64; ++d) s += sXlast[part * 64 + d] * wq[d * H_];
            sQpart[part * 64 + h] = s;
        }
        BAR_SYNC(1, 128);
        if (wid < 2) {  // tid < 64
            sQ[tid] = rrelu(sQpart[tid] + sQpart[64 + tid] + bq[tid]);
        }
        BAR_SYNC(1, 128);

        for (int tl = 0; tl < ntiles; ++tl) {
            int tbase = start + tl * TILE_M;
            float* sScore = tl ? sScore1 : sScore0;
            uint32_t a_row0 = sb + X0_OFF + (uint32_t)(tl * 32768)
                            + (uint32_t)((kw * 32 + roff) * 256);
            uint32_t a_row1 = a_row0 + 16 * 256;

            float acc[2][8][4];
#pragma unroll
            for (int ms = 0; ms < 2; ++ms)
#pragma unroll
                for (int n = 0; n < 8; ++n)
#pragma unroll
                    for (int i = 0; i < 4; ++i) acc[ms][n][i] = 0.f;

#pragma unroll
            for (int ks = 0; ks < 8; ++ks) {
                uint32_t aoff = (uint32_t)((((2 * ks + ci) ^ rm)) << 4);
                uint32_t a00, a01, a02, a03, a10, a11, a12, a13;
                LDSM_X4(a00, a01, a02, a03, a_row0 + aoff);
                LDSM_X4(a10, a11, a12, a13, a_row1 + aoff);
                uint32_t wh_row = sb + WH_OFF + (uint32_t)((ks * 16 + roff) * 256);
#pragma unroll
                for (int ntp = 0; ntp < 4; ++ntp) {
                    uint32_t boff = (uint32_t)(((nchunk + 2 * ntp + ci) ^ rm) << 4);
                    uint32_t b0, b1, b2, b3;
                    LDSM_X4_T(b0, b1, b2, b3, wh_row + boff);
                    mma_f16(acc[0][2 * ntp],     a00, a01, a02, a03, b0, b1);
                    mma_f16(acc[0][2 * ntp + 1], a00, a01, a02, a03, b2, b3);
                    mma_f16(acc[1][2 * ntp],     a10, a11, a12, a13, b0, b1);
                    mma_f16(acc[1][2 * ntp + 1], a10, a11, a12, a13, b2, b3);
                }
            }

            // scores for this warp's 32 rows
#pragma unroll
            for (int ms = 0; ms < 2; ++ms) {
                float s0 = 0.f, s1 = 0.f;
#pragma unroll
                for (int nt = 0; nt < 8; ++nt) {
                    int c0 = 8 * nt + 2 * t, c1 = c0 + 1;
                    float q0 = sQ[c0], q1 = sQ[c1];
                    float b0 = sBias[c0], b1 = sBias[c1];
                    s0 += q0 * rrelu(acc[ms][nt][0] + b0) + q1 * rrelu(acc[ms][nt][1] + b1);
                    s1 += q0 * rrelu(acc[ms][nt][2] + b0) + q1 * rrelu(acc[ms][nt][3] + b1);
                }
                s0 += __shfl_xor_sync(0xffffffffu, s0, 1);
                s0 += __shfl_xor_sync(0xffffffffu, s0, 2);
                s1 += __shfl_xor_sync(0xffffffffu, s1, 1);
                s1 += __shfl_xor_sync(0xffffffffu, s1, 2);
                if (t == 0) {
                    int r0 = kw * 32 + ms * 16 + g, r1 = r0 + 8;
                    sScore[r0] = (tbase + r0 < len) ? s0 : -INFINITY;
                    sScore[r1] = (tbase + r1 < len) ? s1 : -INFINITY;
                }
            }
            BAR_SYNC(1, 128);   // all K scores of this tile visible

            // softmax reduce (warp 0 writes m/sum for V + final merge)
            if (wid == 0) {
                float v0 = sScore[lane], v1 = sScore[lane + 32];
                float v2 = sScore[lane + 64], v3 = sScore[lane + 96];
                float mx = fmaxf(fmaxf(v0, v1), fmaxf(v2, v3));
#pragma unroll
                for (int o = 16; o >= 1; o >>= 1)
                    mx = fmaxf(mx, __shfl_xor_sync(0xffffffffu, mx, o));
                float sum = __expf(v0 - mx) + __expf(v1 - mx)
                          + __expf(v2 - mx) + __expf(v3 - mx);
#pragma unroll
                for (int o = 16; o >= 1; o >>= 1)
                    sum += __shfl_xor_sync(0xffffffffu, sum, o);
                if (lane == 0) { sM[tl] = mx; sSum[tl] = sum; }
            }
            MEMBAR_CTA();
            BAR_ARRIVE(2 + tl, 256);   // release V-warps for this tile
        }
    } else {
        // =================== V-warp pipeline (warps 4-7) ===================
        for (int tl = 0; tl < ntiles; ++tl) {
            float* sScore = tl ? sScore1 : sScore0;
            float* sRed   = tl ? sRed1 : sRed0;
            uint32_t a_row0 = sb + X0_OFF + (uint32_t)(tl * 32768)
                            + (uint32_t)((kw * 32 + roff) * 256);
            uint32_t a_row1 = a_row0 + 16 * 256;

            float acc[2][8][4];
#pragma unroll
            for (int ms = 0; ms < 2; ++ms)
#pragma unroll
                for (int n = 0; n < 8; ++n)
#pragma unroll
                    for (int i = 0; i < 4; ++i) acc[ms][n][i] = 0.f;

#pragma unroll
            for (int ks = 0; ks < 8; ++ks) {
                uint32_t aoff = (uint32_t)((((2 * ks + ci) ^ rm)) << 4);
                uint32_t a00, a01, a02, a03, a10, a11, a12, a13;
                LDSM_X4(a00, a01, a02, a03, a_row0 + aoff);
                LDSM_X4(a10, a11, a12, a13, a_row1 + aoff);
                uint32_t wh_row = sb + WH_OFF + (uint32_t)((ks * 16 + roff) * 256);
#pragma unroll
                for (int ntp = 0; ntp < 4; ++ntp) {
                    uint32_t boff = (uint32_t)(((nchunk + 2 * ntp + ci) ^ rm) << 4);
                    uint32_t b0, b1, b2, b3;
                    LDSM_X4_T(b0, b1, b2, b3, wh_row + boff);
                    mma_f16(acc[0][2 * ntp],     a00, a01, a02, a03, b0, b1);
                    mma_f16(acc[0][2 * ntp + 1], a00, a01, a02, a03, b2, b3);
                    mma_f16(acc[1][2 * ntp],     a10, a11, a12, a13, b0, b1);
                    mma_f16(acc[1][2 * ntp + 1], a10, a11, a12, a13, b2, b3);
                }
            }

            BAR_SYNC(2 + tl, 256);   // wait for K-warps' softmax of this tile

            float mx = sM[tl];
            int rbase = kw * 32;
            float wa = __expf(sScore[rbase + g]      - mx);
            float wb = __expf(sScore[rbase + g + 8]  - mx);
            float wc = __expf(sScore[rbase + g + 16] - mx);
            float wd = __expf(sScore[rbase + g + 24] - mx);
#pragma unroll
            for (int nt = 0; nt < 8; ++nt) {
                int c0 = 8 * nt + 2 * t, c1 = c0 + 1;
                float b0 = sBias[64 + c0], b1 = sBias[64 + c1];
                float p0 = wa * rrelu(acc[0][nt][0] + b0) + wb * rrelu(acc[0][nt][2] + b0)
                         + wc * rrelu(acc[1][nt][0] + b0) + wd * rrelu(acc[1][nt][2] + b0);
                float p1 = wa * rrelu(acc[0][nt][1] + b1) + wb * rrelu(acc[0][nt][3] + b1)
                         + wc * rrelu(acc[1][nt][1] + b1) + wd * rrelu(acc[1][nt][3] + b1);
                p0 += __shfl_xor_sync(0xffffffffu, p0, 4);
                p0 += __shfl_xor_sync(0xffffffffu, p0, 8);
                p0 += __shfl_xor_sync(0xffffffffu, p0, 16);
                p1 += __shfl_xor_sync(0xffffffffu, p1, 4);
                p1 += __shfl_xor_sync(0xffffffffu, p1, 8);
                p1 += __shfl_xor_sync(0xffffffffu, p1, 16);
                if (g == 0) {
                    sRed[kw * 64 + c0] = p0;
                    sRed[kw * 64 + c1] = p1;
                }
            }
        }
    }
    __syncthreads();

    // ---- in-block two-tile logsumexp merge ----
    float m0 = sM[0], m1 = sM[1];
    float M = fmaxf(m0, m1);
    float e0 = __expf(m0 - M);
    float e1 = __expf(m1 - M);
    if (tid < H_) {
        float A = (sRed0[tid] + sRed0[64 + tid] + sRed0[128 + tid] + sRed0[192 + tid]) * e0;
        if (ntiles == 2)
            A += (sRed1[tid] + sRed1[64 + tid] + sRed1[128 + tid] + sRed1[192 + tid]) * e1;
        g_acc[idx * H_ + tid] = A;
    }
    if (tid == 0) {
        g_m[idx] = M;
        g_s[idx] = sSum[0] * e0 + sSum[1] * e1;
    }

    // ---- last-block combine (threadfence reduction) ----
    __threadfence();
    __syncthreads();
    if (tid == 0) {
        int old = atomicAdd(&g_cnt[b], 1);
        *sLast = (old == nlive - 1);
    }
    __syncthreads();
    if (*sLast) {
        if (tid < H_) {
            volatile float* vm = g_m + b * NSPLIT;
            volatile float* vs = g_s + b * NSPLIT;
            volatile float* va = g_acc + (size_t)b * NSPLIT * H_;
            float MM = -INFINITY;
            for (int i = 0; i < nlive; ++i) MM = fmaxf(MM, vm[i]);
            float S = 0.f, A = 0.f;
            for (int i = 0; i < nlive; ++i) {
                float e = __expf(vm[i] - MM);
                S += vs[i] * e;
                A += va[i * H_ + tid] * e;
            }
            out[b * H_ + tid] = A / S;
        }
        if (tid == 0) g_cnt[b] = 0;   // reset for next replay
    }
}

// ---------------------------------------------------------------------------
extern "C" void kernel_launch(void* const* d_in, const int* in_sizes, int n_in,
                              void* d_out, int out_size) {
    const float* ts      = (const float*)d_in[0];
    const float* seq     = (const float*)d_in[1];
    const int*   lengths = (const int*)  d_in[2];
    const float* Wk      = (const float*)d_in[3];
    const float* bk      = (const float*)d_in[4];
    const float* Wq      = (const float*)d_in[5];
    const float* bq      = (const float*)d_in[6];
    const float* Wv      = (const float*)d_in[7];
    const float* bv      = (const float*)d_in[8];
    float* out = (float*)d_out;

    static int configured = 0;
    if (!configured) {
        cudaFuncSetAttribute(fused_attn,
                             cudaFuncAttributeMaxDynamicSharedMemorySize, SMEM_TOTAL);
        configured = 1;
    }

    dim3 grid(NSPLIT, B_);
    fused_attn<<<grid, TPB, SMEM_TOTAL>>>(ts, seq, lengths, Wk, bk, Wq, bq, Wv, bv, out);
}